// round 6
// baseline (speedup 1.0000x reference)
#include <cuda_runtime.h>
#include <math.h>

#define N_NODES   8192
#define K_NBR     64
#define TWO_N     (2 * N_NODES)
#define BN_EPS    1e-3f

// Fused GEMV config: grid (8, 64) = 512 blocks (3.46/SM, single wave).
// Chunk = 256 rows. Chunks 0-31: rows<N (h=BN(x)). Chunks 32-63: rows>=N
// (h = BN(x + ngh_sum), gather computed in-block, hidden under the W stream).
#define COL_TILES      8
#define ROW_CHUNKS     64
#define ROWS_PER_CHUNK 256
#define THREADS_B      256

// scratch (no allocation allowed in kernel_launch)
__device__ float g_part[ROW_CHUNKS * N_NODES];

// ---------------------------------------------------------------------------
// Fused K1+K2: build this chunk's h slice in-block, then stream W.
// ---------------------------------------------------------------------------
__global__ __launch_bounds__(THREADS_B)
void gemv_fused_kernel(const float* __restrict__ x,
                       const int* __restrict__ adj,
                       const float* __restrict__ W,
                       const float* __restrict__ gamma,
                       const float* __restrict__ beta,
                       const float* __restrict__ mean,
                       const float* __restrict__ var)
{
    __shared__ float sx[N_NODES];          // 32 KB, only touched by upper chunks
    __shared__ float sh[ROWS_PER_CHUNK];   // this chunk's h values

    const int tid     = threadIdx.x;
    const int colBase = blockIdx.x * (THREADS_B * 4) + tid * 4;
    const int rowBase = blockIdx.y * ROWS_PER_CHUNK;
    const int row     = rowBase + tid;

    if (blockIdx.y < ROW_CHUNKS / 2) {
        // ---- lower half: h = BN(x[row]); start streaming W almost instantly
        sh[tid] = x[row];
    } else {
        // ---- upper half: need ngh_sum for nodes [nodeBase0, +256)
        // preload x into smem: 2048 float4 / 256 threads = 8 each
        {
            const float4* x4 = reinterpret_cast<const float4*>(x);
            float4* s4 = reinterpret_cast<float4*>(sx);
            #pragma unroll
            for (int i = 0; i < 8; ++i)
                s4[tid + i * THREADS_B] = x4[tid + i * THREADS_B];
        }
        __syncthreads();

        const int warpId = tid >> 5;
        const int lane   = tid & 31;
        const int nodeBase0 = (blockIdx.y - ROW_CHUNKS / 2) * ROWS_PER_CHUNK;
        const int warpNode  = nodeBase0 + warpId * 32;   // 32 nodes per warp
        const int2* adj2 = reinterpret_cast<const int2*>(adj);

        #pragma unroll
        for (int g = 0; g < 32; g += 4) {
            float s[4];
            #pragma unroll
            for (int i = 0; i < 4; ++i) {
                int2 a = adj2[(warpNode + g + i) * 32 + lane];
                s[i] = sx[a.x] + sx[a.y];
            }
            #pragma unroll
            for (int off = 16; off > 0; off >>= 1) {
                #pragma unroll
                for (int i = 0; i < 4; ++i)
                    s[i] += __shfl_down_sync(0xffffffffu, s[i], off);
            }
            if (lane == 0) {
                #pragma unroll
                for (int i = 0; i < 4; ++i) {
                    int node = warpNode + g + i;
                    sh[warpId * 32 + g + i] = sx[node] + s[i];   // agg
                }
            }
        }
    }
    __syncthreads();

    // ---- unified BN pass (coalesced param loads), each thread its own slot
    {
        float v   = sh[tid];
        float inv = rsqrtf(var[row] + BN_EPS);
        float hb  = (v - mean[row]) * inv * gamma[row] + beta[row];
        __syncthreads();           // everyone done reading sh (paranoia: own slot only, but cheap)
        sh[tid] = hb;
    }
    __syncthreads();

    // ---- stream W: proven R2 inner loop (coalesced float4, unroll 8)
    float4 acc = make_float4(0.f, 0.f, 0.f, 0.f);
    const float* wp = W + (long long)rowBase * N_NODES + colBase;

    #pragma unroll 8
    for (int r = 0; r < ROWS_PER_CHUNK; ++r) {
        float  hv = sh[r];
        float4 w  = *reinterpret_cast<const float4*>(wp);
        acc.x = fmaf(hv, w.x, acc.x);
        acc.y = fmaf(hv, w.y, acc.y);
        acc.z = fmaf(hv, w.z, acc.z);
        acc.w = fmaf(hv, w.w, acc.w);
        wp += N_NODES;
    }

    *reinterpret_cast<float4*>(&g_part[blockIdx.y * N_NODES + colBase]) = acc;
}

// ---------------------------------------------------------------------------
// K3: reduce 64 partials (2MB, L2-resident), add bias, exact-erf gelu.
// ---------------------------------------------------------------------------
__global__ void reduce_gelu_kernel(const float* __restrict__ bias,
                                   float* __restrict__ out)
{
    const int j = blockIdx.x * blockDim.x + threadIdx.x;
    if (j >= N_NODES) return;

    float s = 0.f;
    #pragma unroll 16
    for (int c = 0; c < ROW_CHUNKS; ++c)
        s += g_part[c * N_NODES + j];

    float z = s + bias[j];
    out[j] = 0.5f * z * (1.0f + erff(z * 0.70710678118654752440f));
}

// ---------------------------------------------------------------------------
extern "C" void kernel_launch(void* const* d_in, const int* in_sizes, int n_in,
                              void* d_out, int out_size)
{
    const float* x     = (const float*)d_in[0];  // input_data [1,N]
    const int*   adj   = (const int*)d_in[1];    // adj [N,K] int32 (JAX x64 off)
    // d_in[2] = edge_weights (unused by reference)
    const float* W     = (const float*)d_in[3];  // [2N, N]
    const float* b     = (const float*)d_in[4];  // [N]
    const float* gamma = (const float*)d_in[5];  // [2N]
    const float* beta  = (const float*)d_in[6];  // [2N]
    const float* mean  = (const float*)d_in[7];  // [2N]
    const float* var   = (const float*)d_in[8];  // [2N]
    float*       out   = (float*)d_out;

    dim3 grid(COL_TILES, ROW_CHUNKS);
    gemv_fused_kernel<<<grid, THREADS_B>>>(x, adj, W, gamma, beta, mean, var);

    reduce_gelu_kernel<<<(N_NODES + 255) / 256, 256>>>(b, out);
}

// round 7
// speedup vs baseline: 1.3272x; 1.3272x over previous
#include <cuda_runtime.h>
#include <math.h>

#define N_NODES   8192
#define K_NBR     64
#define TWO_N     (2 * N_NODES)
#define BN_EPS    1e-3f

// K2 (proven R2 config): grid (8, 64), 256-row chunks, 256 threads
#define COL_TILES      8
#define ROW_CHUNKS     64
#define ROWS_PER_CHUNK 256
#define THREADS_B      256

// K1: 32 blocks x 1024 threads, 8 nodes per warp (32*32*8 = 8192)
#define K1_BLOCKS   32
#define K1_THREADS  1024
#define NPW         8

// scratch (no allocation allowed in kernel_launch)
__device__ float g_h[TWO_N];
__device__ float g_part[ROW_CHUNKS * N_NODES];

// ---------------------------------------------------------------------------
// K1: gather from SMEM-resident x with deep ILP.
// 8 nodes/warp: 8 batched adj LDG.64, 16 smem gathers, 8 interleaved
// shuffle-reduction chains (hides the ~8cyc shuffle latency completely).
// ---------------------------------------------------------------------------
__global__ __launch_bounds__(K1_THREADS)
void build_h_kernel(const float* __restrict__ x,
                    const int* __restrict__ adj,
                    const float* __restrict__ gamma,
                    const float* __restrict__ beta,
                    const float* __restrict__ mean,
                    const float* __restrict__ var)
{
    __shared__ float sx[N_NODES];   // 32 KB

    // preload x: 2048 float4 / 1024 threads = 2 each
    {
        const float4* x4 = reinterpret_cast<const float4*>(x);
        float4* s4 = reinterpret_cast<float4*>(sx);
        s4[threadIdx.x]        = x4[threadIdx.x];
        s4[threadIdx.x + 1024] = x4[threadIdx.x + 1024];
    }
    __syncthreads();

    const int warpId   = threadIdx.x >> 5;
    const int lane     = threadIdx.x & 31;
    const int nodeBase = blockIdx.x * 256 + warpId * NPW;

    const int2* adj2 = reinterpret_cast<const int2*>(adj);
    int2 a[NPW];
    #pragma unroll
    for (int i = 0; i < NPW; ++i)
        a[i] = adj2[(nodeBase + i) * 32 + lane];     // 8 LDG.64 in flight

    float s[NPW];
    #pragma unroll
    for (int i = 0; i < NPW; ++i)
        s[i] = sx[a[i].x] + sx[a[i].y];

    #pragma unroll
    for (int off = 16; off > 0; off >>= 1) {
        #pragma unroll
        for (int i = 0; i < NPW; ++i)
            s[i] += __shfl_down_sync(0xffffffffu, s[i], off);
    }

    if (lane == 0) {
        #pragma unroll
        for (int i = 0; i < NPW; ++i) {
            const int node = nodeBase + i;
            float xv = sx[node];
            {   // BN for h[node] (raw x part)
                float inv = rsqrtf(var[node] + BN_EPS);
                g_h[node] = (xv - mean[node]) * inv * gamma[node] + beta[node];
            }
            {   // BN for h[N + node] (agg part)
                int j = N_NODES + node;
                float agg = xv + s[i];
                float inv = rsqrtf(var[j] + BN_EPS);
                g_h[j] = (agg - mean[j]) * inv * gamma[j] + beta[j];
            }
        }
    }
}

// ---------------------------------------------------------------------------
// K2: split-K GEMV partials — byte-identical to the R2 kernel that measured
// ~75.4us (~6.8 TB/s). grid (8,64), smem-cached h chunk, coalesced float4
// stream of W, unroll 8. Each partial written once -> deterministic.
// ---------------------------------------------------------------------------
__global__ __launch_bounds__(THREADS_B)
void gemv_partial_kernel(const float* __restrict__ W)
{
    __shared__ float sh[ROWS_PER_CHUNK];

    const int colBase = blockIdx.x * (THREADS_B * 4) + threadIdx.x * 4;
    const int rowBase = blockIdx.y * ROWS_PER_CHUNK;

    sh[threadIdx.x] = g_h[rowBase + threadIdx.x];
    __syncthreads();

    float4 acc = make_float4(0.f, 0.f, 0.f, 0.f);
    const float* wp = W + (long long)rowBase * N_NODES + colBase;

    #pragma unroll 8
    for (int r = 0; r < ROWS_PER_CHUNK; ++r) {
        float hv = sh[r];
        float4 w = *reinterpret_cast<const float4*>(wp);
        acc.x = fmaf(hv, w.x, acc.x);
        acc.y = fmaf(hv, w.y, acc.y);
        acc.z = fmaf(hv, w.z, acc.z);
        acc.w = fmaf(hv, w.w, acc.w);
        wp += N_NODES;
    }

    *reinterpret_cast<float4*>(&g_part[(long long)blockIdx.y * N_NODES + colBase]) = acc;
}

// ---------------------------------------------------------------------------
// K3: two-level parallel reduce. grid 32 x 1024 threads.
// Thread (cg = tid>>8, jLocal = tid&255) sums 16 chunks (coalesced over
// jLocal), combine via smem, 256 threads finish bias + exact-erf gelu.
// ---------------------------------------------------------------------------
__global__ __launch_bounds__(1024)
void reduce_gelu_kernel(const float* __restrict__ bias,
                        float* __restrict__ out)
{
    __shared__ float red[4][256];

    const int jLocal = threadIdx.x & 255;
    const int cg     = threadIdx.x >> 8;          // 0..3
    const int j      = blockIdx.x * 256 + jLocal;

    float s = 0.f;
    #pragma unroll
    for (int i = 0; i < ROW_CHUNKS / 4; ++i) {    // 16 chunks per thread
        int c = cg * (ROW_CHUNKS / 4) + i;
        s += g_part[c * N_NODES + j];
    }
    red[cg][jLocal] = s;
    __syncthreads();

    if (threadIdx.x < 256) {
        float t = red[0][jLocal] + red[1][jLocal] + red[2][jLocal] + red[3][jLocal];
        float z = t + bias[j];
        out[j] = 0.5f * z * (1.0f + erff(z * 0.70710678118654752440f));
    }
}

// ---------------------------------------------------------------------------
extern "C" void kernel_launch(void* const* d_in, const int* in_sizes, int n_in,
                              void* d_out, int out_size)
{
    const float* x     = (const float*)d_in[0];  // input_data [1,N]
    const int*   adj   = (const int*)d_in[1];    // adj [N,K] int32 (JAX x64 off)
    // d_in[2] = edge_weights (unused by reference)
    const float* W     = (const float*)d_in[3];  // [2N, N]
    const float* b     = (const float*)d_in[4];  // [N]
    const float* gamma = (const float*)d_in[5];  // [2N]
    const float* beta  = (const float*)d_in[6];  // [2N]
    const float* mean  = (const float*)d_in[7];  // [2N]
    const float* var   = (const float*)d_in[8];  // [2N]
    float*       out   = (float*)d_out;

    build_h_kernel<<<K1_BLOCKS, K1_THREADS>>>(x, adj, gamma, beta, mean, var);

    dim3 grid2(COL_TILES, ROW_CHUNKS);
    gemv_partial_kernel<<<grid2, THREADS_B>>>(W);

    reduce_gelu_kernel<<<N_NODES / 256, 1024>>>(b, out);
}

// round 8
// speedup vs baseline: 1.3891x; 1.0466x over previous
#include <cuda_runtime.h>
#include <math.h>

#define N_NODES   8192
#define K_NBR     64
#define TWO_N     (2 * N_NODES)
#define BN_EPS    1e-3f

// Fused kernel: 64 builder blocks + 512 GEMV blocks = 576 blocks, all
// co-resident (<= 148 SMs * 4 blocks at 256 threads / ~48 regs / 1KB smem),
// so the flag spin can never deadlock.
#define N_BUILDERS     64
#define NODES_PER_B    (N_NODES / N_BUILDERS)   // 128
#define COL_TILES      8
#define ROW_CHUNKS     64
#define ROWS_PER_CHUNK 256
#define THREADS_B      256
#define GRID_TOTAL     (N_BUILDERS + COL_TILES * ROW_CHUNKS)

// scratch (no allocation allowed in kernel_launch). Zero-initialized at load;
// flags/counters are self-resetting each execution -> graph-replay safe.
__device__ float g_h[TWO_N];                     // only rows >= N used
__device__ float g_part[ROW_CHUNKS * N_NODES];
__device__ int   g_flag[N_BUILDERS];
__device__ int   g_cnt[N_BUILDERS];

// ---------------------------------------------------------------------------
// Fused builder + split-K GEMV.
// ---------------------------------------------------------------------------
__global__ __launch_bounds__(THREADS_B)
void fused_kernel(const float* __restrict__ x,
                  const int* __restrict__ adj,
                  const float* __restrict__ W,
                  const float* __restrict__ gamma,
                  const float* __restrict__ beta,
                  const float* __restrict__ mean,
                  const float* __restrict__ var)
{
    __shared__ float sh[ROWS_PER_CHUNK];
    const int tid = threadIdx.x;

    if (blockIdx.x < N_BUILDERS) {
        // ================= builder: BN(x + ngh_sum) for 128 nodes ==========
        const int b        = blockIdx.x;
        const int warpId   = tid >> 5;
        const int lane     = tid & 31;
        const int nodeBase = b * NODES_PER_B + warpId * 16;   // 16 nodes/warp
        const int2* adj2   = reinterpret_cast<const int2*>(adj);

        #pragma unroll
        for (int g = 0; g < 16; g += 8) {
            int2 a[8];
            #pragma unroll
            for (int i = 0; i < 8; ++i)
                a[i] = __ldg(&adj2[(nodeBase + g + i) * 32 + lane]);

            float s[8];
            #pragma unroll
            for (int i = 0; i < 8; ++i)
                s[i] = __ldg(&x[a[i].x]) + __ldg(&x[a[i].y]);

            #pragma unroll
            for (int off = 16; off > 0; off >>= 1) {
                #pragma unroll
                for (int i = 0; i < 8; ++i)
                    s[i] += __shfl_down_sync(0xffffffffu, s[i], off);
            }

            if (lane == 0) {
                #pragma unroll
                for (int i = 0; i < 8; ++i) {
                    const int node = nodeBase + g + i;
                    const int j    = N_NODES + node;
                    float agg = __ldg(&x[node]) + s[i];
                    float inv = rsqrtf(var[j] + BN_EPS);
                    g_h[j] = (agg - mean[j]) * inv * gamma[j] + beta[j];
                }
            }
        }

        __threadfence();     // make this thread's h writes GPU-visible
        __syncthreads();     // all threads' writes done + fenced
        if (tid == 0)
            atomicExch(&g_flag[b], 1);   // release
        return;
    }

    // ================= GEMV block ==========================================
    const int gid     = blockIdx.x - N_BUILDERS;
    const int colTile = gid & (COL_TILES - 1);
    const int chunk   = gid >> 3;                 // 0..63
    const int colBase = colTile * (THREADS_B * 4) + tid * 4;
    const int rowBase = chunk * ROWS_PER_CHUNK;
    const int row     = rowBase + tid;

    if (chunk < ROW_CHUNKS / 2) {
        // lower half: h = BN(x[row]) computed inline -> no wait, stream now
        float v   = x[row];
        float inv = rsqrtf(var[row] + BN_EPS);
        sh[tid] = (v - mean[row]) * inv * gamma[row] + beta[row];
        __syncthreads();
    } else {
        // upper half: wait for the two builders covering rows [rowBase, +256)
        const int f0 = 2 * (chunk - ROW_CHUNKS / 2);
        if (tid == 0) {
            while (atomicAdd(&g_flag[f0], 0) == 0)     __nanosleep(64);
            while (atomicAdd(&g_flag[f0 + 1], 0) == 0) __nanosleep(64);
            __threadfence();   // acquire
        }
        __syncthreads();
        sh[tid] = __ldcg(&g_h[row]);   // L2 read, builders already applied BN
        __syncthreads();
        // self-resetting consumption (8 consumer blocks per flag)
        if (tid == 0) {
            if (atomicAdd(&g_cnt[f0], 1) == COL_TILES - 1) {
                atomicExch(&g_cnt[f0], 0);
                atomicExch(&g_flag[f0], 0);
            }
            if (atomicAdd(&g_cnt[f0 + 1], 1) == COL_TILES - 1) {
                atomicExch(&g_cnt[f0 + 1], 0);
                atomicExch(&g_flag[f0 + 1], 0);
            }
        }
    }

    // ---- stream W: proven inner loop (coalesced float4, unroll 8) --------
    float4 acc = make_float4(0.f, 0.f, 0.f, 0.f);
    const float* wp = W + (long long)rowBase * N_NODES + colBase;

    #pragma unroll 8
    for (int r = 0; r < ROWS_PER_CHUNK; ++r) {
        float  hv = sh[r];
        float4 w  = *reinterpret_cast<const float4*>(wp);
        acc.x = fmaf(hv, w.x, acc.x);
        acc.y = fmaf(hv, w.y, acc.y);
        acc.z = fmaf(hv, w.z, acc.z);
        acc.w = fmaf(hv, w.w, acc.w);
        wp += N_NODES;
    }

    *reinterpret_cast<float4*>(&g_part[chunk * N_NODES + colBase]) = acc;
}

// ---------------------------------------------------------------------------
// K3: two-level parallel reduce + bias + exact-erf gelu.
// ---------------------------------------------------------------------------
__global__ __launch_bounds__(1024)
void reduce_gelu_kernel(const float* __restrict__ bias,
                        float* __restrict__ out)
{
    __shared__ float red[4][256];

    const int jLocal = threadIdx.x & 255;
    const int cg     = threadIdx.x >> 8;          // 0..3
    const int j      = blockIdx.x * 256 + jLocal;

    float s = 0.f;
    #pragma unroll
    for (int i = 0; i < ROW_CHUNKS / 4; ++i) {
        int c = cg * (ROW_CHUNKS / 4) + i;
        s += g_part[c * N_NODES + j];
    }
    red[cg][jLocal] = s;
    __syncthreads();

    if (threadIdx.x < 256) {
        float t = red[0][jLocal] + red[1][jLocal] + red[2][jLocal] + red[3][jLocal];
        float z = t + bias[j];
        out[j] = 0.5f * z * (1.0f + erff(z * 0.70710678118654752440f));
    }
}

// ---------------------------------------------------------------------------
extern "C" void kernel_launch(void* const* d_in, const int* in_sizes, int n_in,
                              void* d_out, int out_size)
{
    const float* x     = (const float*)d_in[0];  // input_data [1,N]
    const int*   adj   = (const int*)d_in[1];    // adj [N,K] int32 (JAX x64 off)
    // d_in[2] = edge_weights (unused by reference)
    const float* W     = (const float*)d_in[3];  // [2N, N]
    const float* b     = (const float*)d_in[4];  // [N]
    const float* gamma = (const float*)d_in[5];  // [2N]
    const float* beta  = (const float*)d_in[6];  // [2N]
    const float* mean  = (const float*)d_in[7];  // [2N]
    const float* var   = (const float*)d_in[8];  // [2N]
    float*       out   = (float*)d_out;

    fused_kernel<<<GRID_TOTAL, THREADS_B>>>(x, adj, W, gamma, beta, mean, var);

    reduce_gelu_kernel<<<N_NODES / 256, 1024>>>(b, out);
}